// round 5
// baseline (speedup 1.0000x reference)
#include <cuda_runtime.h>
#include <cuda_bf16.h>
#include <math.h>
#include <cstdint>

#define NN 16384
#define CC 256
#define HH 8
#define HD 512
#define QKVW 1536
#define HIDD 512
#define OUTD 64
#define H2D 532
#define ATTKP 576   // 520 padded to 64-multiple
#define H2KP 576    // 532 padded

// ---------------- scratch (static device arrays; no allocation) ----------------
__device__ float g_QKV[NN * QKVW];          // fp32 Q|K|V for attention
__device__ float g_G[NN * HH];
__device__ float g_Z[NN * OUTD];
__device__ double g_loss;

// activation bf16 limbs (zero-init pads stay zero forever)
__device__ __nv_bfloat16 g_xl0[NN * CC], g_xl1[NN * CC], g_xl2[NN * CC];
__device__ __nv_bfloat16 g_Al0[NN * ATTKP], g_Al1[NN * ATTKP], g_Al2[NN * ATTKP];
__device__ __nv_bfloat16 g_Tl0[NN * CC], g_Tl1[NN * CC], g_Tl2[NN * CC];
__device__ __nv_bfloat16 g_Hl0[NN * H2KP], g_Hl1[NN * H2KP], g_Hl2[NN * H2KP];

// weight bf16 limbs, [N, Kp] K-major
__device__ __nv_bfloat16 g_Bq0[QKVW * CC], g_Bq1[QKVW * CC], g_Bq2[QKVW * CC];
__device__ __nv_bfloat16 g_Bo0[CC * ATTKP], g_Bo1[CC * ATTKP], g_Bo2[CC * ATTKP];
__device__ __nv_bfloat16 g_Bl0[HIDD * CC], g_Bl1[HIDD * CC], g_Bl2[HIDD * CC];
__device__ __nv_bfloat16 g_Bu0[OUTD * H2KP], g_Bu1[OUTD * H2KP], g_Bu2[OUTD * H2KP];

// ---------------- helpers ----------------
__device__ __forceinline__ float gelu_tanh(float x) {
    float x3 = x * x * x;
    return 0.5f * x * (1.0f + tanhf(0.7978845608028654f * (x + 0.044715f * x3)));
}

__device__ __forceinline__ void split3(float v, __nv_bfloat16& b0, __nv_bfloat16& b1,
                                       __nv_bfloat16& b2) {
    b0 = __float2bfloat16(v);
    float r = v - __bfloat162float(b0);
    b1 = __float2bfloat16(r);
    float r2 = r - __bfloat162float(b1);
    b2 = __float2bfloat16(r2);
}

__device__ __forceinline__ void store3(__nv_bfloat16* p0, __nv_bfloat16* p1,
                                       __nv_bfloat16* p2, size_t off, float v) {
    __nv_bfloat16 b0, b1, b2;
    split3(v, b0, b1, b2);
    p0[off] = b0; p1[off] = b1; p2[off] = b2;
}

__device__ __forceinline__ uint32_t smem_u32(const void* p) {
    uint32_t a;
    asm("{ .reg .u64 t; cvta.to.shared.u64 t, %1; cvt.u32.u64 %0, t; }" : "=r"(a) : "l"(p));
    return a;
}

__device__ __forceinline__ void ldsm4(uint32_t* r, uint32_t addr) {
    asm volatile("ldmatrix.sync.aligned.m8n8.x4.shared.b16 {%0,%1,%2,%3}, [%4];"
                 : "=r"(r[0]), "=r"(r[1]), "=r"(r[2]), "=r"(r[3]) : "r"(addr));
}

__device__ __forceinline__ void mma16816(float* c, const uint32_t* a, const uint32_t* b) {
    asm volatile(
        "mma.sync.aligned.m16n8k16.row.col.f32.bf16.bf16.f32 "
        "{%0,%1,%2,%3}, {%4,%5,%6,%7}, {%8,%9}, {%0,%1,%2,%3};"
        : "+f"(c[0]), "+f"(c[1]), "+f"(c[2]), "+f"(c[3])
        : "r"(a[0]), "r"(a[1]), "r"(a[2]), "r"(a[3]), "r"(b[0]), "r"(b[1]));
}

// ============== mma.sync bf16 3-limb GEMM: C = A*B^T ==============
// A limbs: [M, Kp] row-major bf16.  B limbs: [N, Kp] K-major bf16.
// CTA tile 128 x NT, 8 warps (2m x 4n), warp tile 64 x (NT/4).
// EPI: 0=fp32 plain, 1=resid+dyntanh->limbs, 2=gelu(bias)+dyntanh->limbs,
//      3=tanh(gelu(bias))->fp32
template <int NT, int EPI>
__global__ __launch_bounds__(256) void mmagemm(
        const __nv_bfloat16* __restrict__ A0, const __nv_bfloat16* __restrict__ A1,
        const __nv_bfloat16* __restrict__ A2,
        const __nv_bfloat16* __restrict__ B0, const __nv_bfloat16* __restrict__ B1,
        const __nv_bfloat16* __restrict__ B2,
        int Kp,
        float* __restrict__ outF, int ldoF,
        __nv_bfloat16* __restrict__ O0, __nv_bfloat16* __restrict__ O1,
        __nv_bfloat16* __restrict__ O2, int ldoL,
        const float* __restrict__ bias, const float* __restrict__ resid, int ldr,
        const float* __restrict__ alpha_p,
        const float* __restrict__ gv, const float* __restrict__ bv) {
    __shared__ __nv_bfloat16 As[128][72];
    __shared__ __nv_bfloat16 Bs[NT][72];
    constexpr int NF = NT / 32;   // n-frags per warp (8 cols each)

    int tid = threadIdx.x, lane = tid & 31, wid = tid >> 5;
    int wm = wid & 1, wn = wid >> 1;
    int bm = blockIdx.y * 128, bn = blockIdx.x * NT;
    int nch = Kp >> 6;

    float acc[4][NF][4];
#pragma unroll
    for (int i = 0; i < 4; i++)
#pragma unroll
        for (int j = 0; j < NF; j++)
#pragma unroll
            for (int c = 0; c < 4; c++) acc[i][j][c] = 0.f;

    const int laT[6] = {0, 0, 0, 1, 1, 2};
    const int lbT[6] = {0, 1, 2, 0, 1, 0};

#pragma unroll 1
    for (int t = 0; t < 6; t++) {
        const __nv_bfloat16* Ab = (laT[t] == 0) ? A0 : ((laT[t] == 1) ? A1 : A2);
        const __nv_bfloat16* Bb = (lbT[t] == 0) ? B0 : ((lbT[t] == 1) ? B1 : B2);
#pragma unroll 1
        for (int c = 0; c < nch; c++) {
            __syncthreads();   // previous chunk's compute done
            const __nv_bfloat16* Asrc = Ab + (size_t)bm * Kp + c * 64;
#pragma unroll
            for (int q = 0; q < 4; q++) {
                int idx = tid + q * 256;
                int row = idx >> 3, cg = idx & 7;
                uint4 v = *(const uint4*)(Asrc + (size_t)row * Kp + cg * 8);
                *(uint4*)&As[row][cg * 8] = v;
            }
            const __nv_bfloat16* Bsrc = Bb + (size_t)bn * Kp + c * 64;
#pragma unroll
            for (int q = 0; q < NF; q++) {
                int idx = tid + q * 256;
                int row = idx >> 3, cg = idx & 7;
                uint4 v = *(const uint4*)(Bsrc + (size_t)row * Kp + cg * 8);
                *(uint4*)&Bs[row][cg * 8] = v;
            }
            __syncthreads();

#pragma unroll
            for (int kk = 0; kk < 4; kk++) {
                int k = kk * 16;
                uint32_t a[4][4];
#pragma unroll
                for (int i = 0; i < 4; i++) {
                    int row = wm * 64 + i * 16 + (lane & 15);
                    int col = k + (lane >> 4) * 8;
                    ldsm4(a[i], smem_u32(&As[row][col]));
                }
                uint32_t b[NF][2];
#pragma unroll
                for (int jj = 0; jj < NF / 2; jj++) {
                    int n0 = wn * (NT / 4) + jj * 16;
                    int g = lane >> 3;
                    int nr = n0 + ((g >> 1) << 3) + (lane & 7);
                    int kc = k + (g & 1) * 8;
                    uint32_t tmp[4];
                    ldsm4(tmp, smem_u32(&Bs[nr][kc]));
                    b[2 * jj][0] = tmp[0]; b[2 * jj][1] = tmp[1];
                    b[2 * jj + 1][0] = tmp[2]; b[2 * jj + 1][1] = tmp[3];
                }
#pragma unroll
                for (int i = 0; i < 4; i++)
#pragma unroll
                    for (int j = 0; j < NF; j++) mma16816(acc[i][j], a[i], b[j]);
            }
        }
    }

    // ---------------- epilogue ----------------
    float alpha = (EPI == 1 || EPI == 2) ? *alpha_p : 0.f;
    int gid = lane >> 2, tig = lane & 3;
#pragma unroll
    for (int i = 0; i < 4; i++) {
#pragma unroll
        for (int j = 0; j < NF; j++) {
#pragma unroll
            for (int cc = 0; cc < 4; cc++) {
                int m = bm + wm * 64 + i * 16 + gid + (cc >> 1) * 8;
                int ncol = bn + wn * (NT / 4) + j * 8 + tig * 2 + (cc & 1);
                float v = acc[i][j][cc];
                if (EPI == 0) {
                    outF[(size_t)m * ldoF + ncol] = v;
                } else if (EPI == 1) {
                    v += resid[(size_t)m * ldr + ncol];
                    v = tanhf(alpha * v) * gv[ncol] + bv[ncol];
                    store3(O0, O1, O2, (size_t)m * ldoL + ncol, v);
                } else if (EPI == 2) {
                    v = gelu_tanh(v + bias[ncol]);
                    v = tanhf(alpha * v) * gv[ncol] + bv[ncol];
                    store3(O0, O1, O2, (size_t)m * ldoL + ncol, v);
                } else {
                    v = tanhf(gelu_tanh(v + bias[ncol]));
                    outF[(size_t)m * ldoF + ncol] = v;
                }
            }
        }
    }
}

// ---------------- conversions ----------------
__global__ void convA_kernel(const float* __restrict__ src, __nv_bfloat16* d0,
                             __nv_bfloat16* d1, __nv_bfloat16* d2, int n) {
    int t = blockIdx.x * blockDim.x + threadIdx.x;
    if (t >= n) return;
    store3(d0, d1, d2, t, src[t]);
}

__global__ void convB_kernel(const float* __restrict__ src, __nv_bfloat16* d0,
                             __nv_bfloat16* d1, __nv_bfloat16* d2, int K, int N, int Kp) {
    int t = blockIdx.x * blockDim.x + threadIdx.x;
    if (t >= N * K) return;
    int n = t / K, k = t - n * K;
    store3(d0, d1, d2, (size_t)n * Kp + k, src[(size_t)k * N + n]);
}

__global__ void convBqkv_kernel(const float* __restrict__ Wq, const float* __restrict__ Wk,
                                const float* __restrict__ Wv, __nv_bfloat16* d0,
                                __nv_bfloat16* d1, __nv_bfloat16* d2) {
    int t = blockIdx.x * blockDim.x + threadIdx.x;
    if (t >= QKVW * CC) return;
    int n = t >> 8, k = t & 255;
    const float* s = (n < 512) ? Wq : ((n < 1024) ? Wk : Wv);
    int col = n & 511;
    store3(d0, d1, d2, (size_t)n * CC + k, s[(size_t)k * 512 + col]);
}

// ---------------- gate projection ----------------
__global__ void gate_kernel(const float* __restrict__ x, const float* __restrict__ wg) {
    int t = blockIdx.x * blockDim.x + threadIdx.x;
    if (t >= NN * HH) return;
    int n = t >> 3, h = t & 7;
    const float* xr = x + (size_t)n * CC;
    float acc = 0.f;
#pragma unroll 4
    for (int c = 0; c < CC; c++) acc = fmaf(xr[c], wg[c * HH + h], acc);
    g_G[t] = acc;
}

// ---------------- attention: block per node, warp per head; writes Att limbs ------
__global__ void attn_kernel(const float* __restrict__ coors, const int* __restrict__ nbr,
                            const float* __restrict__ Wr1, const float* __restrict__ br1,
                            const float* __restrict__ Wr2, const float* __restrict__ br2) {
    int n = blockIdx.x;
    int tid = threadIdx.x;
    __shared__ int s_nbr[8];
    __shared__ float s_dist[8];
    __shared__ float s_unit[8][3];
    __shared__ float s_rad[8][8];
    __shared__ float s_gate[8][8];

    if (tid < 8) s_nbr[tid] = nbr[(size_t)n * 8 + tid];
    __syncthreads();
    if (tid < 8) {
        int j = tid;
        float cx = coors[(size_t)n * 3], cy = coors[(size_t)n * 3 + 1], cz = coors[(size_t)n * 3 + 2];
        int mm = s_nbr[j];
        float rx = coors[(size_t)mm * 3] - cx;
        float ry = coors[(size_t)mm * 3 + 1] - cy;
        float rz = coors[(size_t)mm * 3 + 2] - cz;
        float d = sqrtf(rx * rx + ry * ry + rz * rz + 1e-8f);
        s_dist[j] = d;
        s_unit[j][0] = rx / d;
        s_unit[j][1] = ry / d;
        s_unit[j][2] = rz / d;
    }
    __syncthreads();
    if (tid < 64) {
        int j = tid >> 3, h = tid & 7;
        float d = s_dist[j];
        float acc = br2[h];
#pragma unroll
        for (int i = 0; i < 16; i++)
            acc = fmaf(gelu_tanh(d * Wr1[i] + br1[i]), Wr2[i * 8 + h], acc);
        s_rad[j][h] = acc;
        s_gate[j][h] = g_G[(size_t)s_nbr[j] * HH + h];
    }
    __syncthreads();

    int w = tid >> 5, lane = tid & 31;
    int h = w;
    const float* qr = g_QKV + (size_t)n * QKVW + h * 64;
    float q0 = qr[lane * 2], q1 = qr[lane * 2 + 1];
    float logit[8];
#pragma unroll
    for (int j = 0; j < 8; j++) {
        const float* kr = g_QKV + (size_t)s_nbr[j] * QKVW + 512 + h * 64;
        float p = q0 * kr[lane * 2] + q1 * kr[lane * 2 + 1];
#pragma unroll
        for (int o = 16; o; o >>= 1) p += __shfl_xor_sync(0xffffffffu, p, o);
        p = p * 0.125f + s_rad[j][h];
        logit[j] = (s_dist[j] <= 10.0f) ? p : -1e9f;
    }
    float mx = logit[0];
#pragma unroll
    for (int j = 1; j < 8; j++) mx = fmaxf(mx, logit[j]);
    float e[8];
    float se = 0.f;
#pragma unroll
    for (int j = 0; j < 8; j++) { e[j] = expf(logit[j] - mx); se += e[j]; }
    float inv = 1.f / se;
    float a0 = 0.f, a1 = 0.f;
#pragma unroll
    for (int j = 0; j < 8; j++) {
        float at = e[j] * inv;
        const float* vr = g_QKV + (size_t)s_nbr[j] * QKVW + 1024 + h * 64;
        a0 = fmaf(at, vr[lane * 2], a0);
        a1 = fmaf(at, vr[lane * 2 + 1], a1);
    }
    size_t base = (size_t)n * ATTKP + h * 64 + lane * 2;
    store3(g_Al0, g_Al1, g_Al2, base, a0);
    store3(g_Al0, g_Al1, g_Al2, base + 1, a1);
    if (lane == 0) {
        float vx = 0.f, vy = 0.f, vz = 0.f;
#pragma unroll
        for (int j = 0; j < 8; j++) {
            float wg = e[j] * inv * s_gate[j][h];
            vx = fmaf(wg, s_unit[j][0], vx);
            vy = fmaf(wg, s_unit[j][1], vy);
            vz = fmaf(wg, s_unit[j][2], vz);
        }
        float vn = sqrtf(vx * vx + vy * vy + vz * vz + 1e-8f);
        store3(g_Al0, g_Al1, g_Al2, (size_t)n * ATTKP + 512 + h, vn);
    }
}

// ---------------- H2 extra columns (aa feats through dyntanh2) -> limbs ----------
__global__ void h2extra_kernel(const float* __restrict__ x, const float* __restrict__ alpha2,
                               const float* __restrict__ g2, const float* __restrict__ b2) {
    int t = blockIdx.x * blockDim.x + threadIdx.x;
    if (t >= NN * 20) return;
    int n = t / 20, j = t % 20;
    float a = *alpha2;
    float v = tanhf(a * x[(size_t)n * CC + j]) * g2[512 + j] + b2[512 + j];
    store3(g_Hl0, g_Hl1, g_Hl2, (size_t)n * H2KP + 512 + j, v);
}

// ---------------- VQ: argmin + quantize + commitment loss ----------------
__global__ void zero_loss_kernel() { g_loss = 0.0; }

__global__ void vq_kernel(const float* __restrict__ cb, float* __restrict__ out) {
    int n = blockIdx.x;
    int t = threadIdx.x;  // 64
    __shared__ float s_z[64];
    __shared__ float s_sc[64];
    __shared__ int s_best;
    s_z[t] = g_Z[(size_t)n * 64 + t];
    __syncthreads();
    float dot = 0.f, cn = 0.f;
    const float* ce = cb + (size_t)t * 64;
#pragma unroll 8
    for (int d = 0; d < 64; d++) {
        float c = ce[d];
        dot = fmaf(s_z[d], c, dot);
        cn = fmaf(c, c, cn);
    }
    s_sc[t] = cn - 2.f * dot;
    __syncthreads();
    if (t == 0) {
        float best = s_sc[0];
        int bi = 0;
        for (int e2 = 1; e2 < 64; e2++)
            if (s_sc[e2] < best) { best = s_sc[e2]; bi = e2; }
        s_best = bi;
    }
    __syncthreads();
    float zq = cb[(size_t)s_best * 64 + t];
    out[(size_t)n * 64 + t] = zq;
    float df = s_z[t] - zq;
    df = df * df;
#pragma unroll
    for (int o = 16; o; o >>= 1) df += __shfl_xor_sync(0xffffffffu, df, o);
    __shared__ float s_part[2];
    if ((t & 31) == 0) s_part[t >> 5] = df;
    __syncthreads();
    if (t == 0) atomicAdd(&g_loss, (double)(s_part[0] + s_part[1]));
}

__global__ void fin_loss_kernel(float* __restrict__ out) {
    out[(size_t)NN * OUTD] = (float)(0.25 * g_loss / (double)((size_t)NN * OUTD));
}

// ---------------- launch ----------------
extern "C" void kernel_launch(void* const* d_in, const int* in_sizes, int n_in,
                              void* d_out, int out_size) {
    const float *x, *coors, *Wq, *Wk, *Wv, *wg, *Wr1, *br1, *Wr2, *br2, *Wo;
    const float *a1, *g1, *b1, *Wlin, *blin, *a2, *g2, *b2, *Wout, *bout, *cb;
    const int* nbr;

    if (n_in > 5 && in_sizes[5] == 2048) {
        x = (const float*)d_in[0];   coors = (const float*)d_in[1];
        Wq = (const float*)d_in[2];  Wk = (const float*)d_in[3];  Wv = (const float*)d_in[4];
        wg = (const float*)d_in[5];  Wr1 = (const float*)d_in[6]; br1 = (const float*)d_in[7];
        Wr2 = (const float*)d_in[8]; br2 = (const float*)d_in[9]; Wo = (const float*)d_in[10];
        a1 = (const float*)d_in[11]; g1 = (const float*)d_in[12]; b1 = (const float*)d_in[13];
        Wlin = (const float*)d_in[14]; blin = (const float*)d_in[15];
        a2 = (const float*)d_in[16]; g2 = (const float*)d_in[17]; b2 = (const float*)d_in[18];
        Wout = (const float*)d_in[19]; bout = (const float*)d_in[20];
        cb = (const float*)d_in[21]; nbr = (const int*)d_in[22];
    } else {
        x = (const float*)d_in[0];   coors = (const float*)d_in[1];
        nbr = (const int*)d_in[2];
        Wq = (const float*)d_in[3];  Wk = (const float*)d_in[4];  Wv = (const float*)d_in[5];
        wg = (const float*)d_in[6];  Wr1 = (const float*)d_in[7]; br1 = (const float*)d_in[8];
        Wr2 = (const float*)d_in[9]; br2 = (const float*)d_in[10]; Wo = (const float*)d_in[11];
        a1 = (const float*)d_in[12]; g1 = (const float*)d_in[13]; b1 = (const float*)d_in[14];
        Wlin = (const float*)d_in[15]; blin = (const float*)d_in[16];
        a2 = (const float*)d_in[17]; g2 = (const float*)d_in[18]; b2 = (const float*)d_in[19];
        Wout = (const float*)d_in[20]; bout = (const float*)d_in[21];
        cb = (const float*)d_in[22];
    }

    float *pQKV, *pZ;
    cudaGetSymbolAddress((void**)&pQKV, g_QKV);
    cudaGetSymbolAddress((void**)&pZ, g_Z);
    __nv_bfloat16 *xl0, *xl1, *xl2, *Al0, *Al1, *Al2, *Tl0, *Tl1, *Tl2, *Hl0, *Hl1, *Hl2;
    cudaGetSymbolAddress((void**)&xl0, g_xl0); cudaGetSymbolAddress((void**)&xl1, g_xl1);
    cudaGetSymbolAddress((void**)&xl2, g_xl2);
    cudaGetSymbolAddress((void**)&Al0, g_Al0); cudaGetSymbolAddress((void**)&Al1, g_Al1);
    cudaGetSymbolAddress((void**)&Al2, g_Al2);
    cudaGetSymbolAddress((void**)&Tl0, g_Tl0); cudaGetSymbolAddress((void**)&Tl1, g_Tl1);
    cudaGetSymbolAddress((void**)&Tl2, g_Tl2);
    cudaGetSymbolAddress((void**)&Hl0, g_Hl0); cudaGetSymbolAddress((void**)&Hl1, g_Hl1);
    cudaGetSymbolAddress((void**)&Hl2, g_Hl2);
    __nv_bfloat16 *Bq0, *Bq1, *Bq2, *Bo0, *Bo1, *Bo2, *Bl0, *Bl1, *Bl2, *Bu0, *Bu1, *Bu2;
    cudaGetSymbolAddress((void**)&Bq0, g_Bq0); cudaGetSymbolAddress((void**)&Bq1, g_Bq1);
    cudaGetSymbolAddress((void**)&Bq2, g_Bq2);
    cudaGetSymbolAddress((void**)&Bo0, g_Bo0); cudaGetSymbolAddress((void**)&Bo1, g_Bo1);
    cudaGetSymbolAddress((void**)&Bo2, g_Bo2);
    cudaGetSymbolAddress((void**)&Bl0, g_Bl0); cudaGetSymbolAddress((void**)&Bl1, g_Bl1);
    cudaGetSymbolAddress((void**)&Bl2, g_Bl2);
    cudaGetSymbolAddress((void**)&Bu0, g_Bu0); cudaGetSymbolAddress((void**)&Bu1, g_Bu1);
    cudaGetSymbolAddress((void**)&Bu2, g_Bu2);

    float* out = (float*)d_out;

    zero_loss_kernel<<<1, 1>>>();

    // conversions: x and weights -> bf16 limbs
    convA_kernel<<<(NN * CC + 255) / 256, 256>>>(x, xl0, xl1, xl2, NN * CC);
    convBqkv_kernel<<<(QKVW * CC + 255) / 256, 256>>>(Wq, Wk, Wv, Bq0, Bq1, Bq2);
    convB_kernel<<<(CC * 520 + 255) / 256, 256>>>(Wo, Bo0, Bo1, Bo2, 520, CC, ATTKP);
    convB_kernel<<<(HIDD * CC + 255) / 256, 256>>>(Wlin, Bl0, Bl1, Bl2, CC, HIDD, CC);
    convB_kernel<<<(OUTD * 532 + 255) / 256, 256>>>(Wout, Bu0, Bu1, Bu2, 532, OUTD, H2KP);

    // QKV = x @ [Wq|Wk|Wv]  -> fp32
    mmagemm<128, 0><<<dim3(QKVW / 128, NN / 128), 256>>>(
        xl0, xl1, xl2, Bq0, Bq1, Bq2, CC,
        pQKV, QKVW, nullptr, nullptr, nullptr, 0,
        nullptr, nullptr, 0, nullptr, nullptr, nullptr);

    gate_kernel<<<(NN * HH + 255) / 256, 256>>>(x, wg);
    attn_kernel<<<NN, 256>>>(coors, nbr, Wr1, br1, Wr2, br2);

    // T = dyntanh(x + Att@Wo) -> limbs
    mmagemm<128, 1><<<dim3(CC / 128, NN / 128), 256>>>(
        Al0, Al1, Al2, Bo0, Bo1, Bo2, ATTKP,
        nullptr, 0, Tl0, Tl1, Tl2, CC,
        nullptr, x, CC, a1, g1, b1);

    // H2[:, :512] = dyntanh2(gelu(T@Wlin + blin)) -> limbs
    mmagemm<128, 2><<<dim3(HIDD / 128, NN / 128), 256>>>(
        Tl0, Tl1, Tl2, Bl0, Bl1, Bl2, CC,
        nullptr, 0, Hl0, Hl1, Hl2, H2KP,
        blin, nullptr, 0, a2, g2, b2);
    h2extra_kernel<<<(NN * 20 + 255) / 256, 256>>>(x, a2, g2, b2);

    // Z = tanh(gelu(H2@Wout + bout)) -> fp32
    mmagemm<64, 3><<<dim3(1, NN / 128), 256>>>(
        Hl0, Hl1, Hl2, Bu0, Bu1, Bu2, H2KP,
        pZ, OUTD, nullptr, nullptr, nullptr, 0,
        bout, nullptr, 0, nullptr, nullptr, nullptr);

    vq_kernel<<<NN, 64>>>(cb, out);
    if (out_size > NN * OUTD) fin_loss_kernel<<<1, 1>>>(out);
}

// round 6
// speedup vs baseline: 1.3341x; 1.3341x over previous
#include <cuda_runtime.h>
#include <cuda_fp16.h>
#include <math.h>
#include <cstdint>

#define NN 16384
#define CC 256
#define HH 8
#define HD 512
#define QKVW 1536
#define HIDD 512
#define OUTD 64
#define H2D 532
#define ATTKP 576   // 520 padded to 64-multiple
#define H2KP 576    // 532 padded

// ---------------- scratch (static device arrays; no allocation) ----------------
__device__ float g_QKV[NN * QKVW];          // fp32 Q|K|V for attention
__device__ float g_G[NN * HH];
__device__ float g_Z[NN * OUTD];
__device__ double g_loss;

// activation fp16 limbs (zero-init pads stay zero forever)
__device__ __half g_xl0[NN * CC], g_xl1[NN * CC];
__device__ __half g_Al0[NN * ATTKP], g_Al1[NN * ATTKP];
__device__ __half g_Tl0[NN * CC], g_Tl1[NN * CC];
__device__ __half g_Hl0[NN * H2KP], g_Hl1[NN * H2KP];

// weight fp16 limbs, [N, Kp] K-major
__device__ __half g_Bq0[QKVW * CC], g_Bq1[QKVW * CC];
__device__ __half g_Bo0[CC * ATTKP], g_Bo1[CC * ATTKP];
__device__ __half g_Bl0[HIDD * CC], g_Bl1[HIDD * CC];
__device__ __half g_Bu0[OUTD * H2KP], g_Bu1[OUTD * H2KP];

// ---------------- helpers ----------------
__device__ __forceinline__ float gelu_tanh(float x) {
    float x3 = x * x * x;
    return 0.5f * x * (1.0f + tanhf(0.7978845608028654f * (x + 0.044715f * x3)));
}

__device__ __forceinline__ void store2(__half* p0, __half* p1, size_t off, float v) {
    __half h0 = __float2half_rn(v);
    __half h1 = __float2half_rn(v - __half2float(h0));
    p0[off] = h0;
    p1[off] = h1;
}

__device__ __forceinline__ uint32_t smem_u32(const void* p) {
    uint32_t a;
    asm("{ .reg .u64 t; cvta.to.shared.u64 t, %1; cvt.u32.u64 %0, t; }" : "=r"(a) : "l"(p));
    return a;
}

__device__ __forceinline__ void ldsm4(uint32_t* r, uint32_t addr) {
    asm volatile("ldmatrix.sync.aligned.m8n8.x4.shared.b16 {%0,%1,%2,%3}, [%4];"
                 : "=r"(r[0]), "=r"(r[1]), "=r"(r[2]), "=r"(r[3]) : "r"(addr));
}

__device__ __forceinline__ void mma16816(float* c, const uint32_t* a, const uint32_t* b) {
    asm volatile(
        "mma.sync.aligned.m16n8k16.row.col.f32.f16.f16.f32 "
        "{%0,%1,%2,%3}, {%4,%5,%6,%7}, {%8,%9}, {%0,%1,%2,%3};"
        : "+f"(c[0]), "+f"(c[1]), "+f"(c[2]), "+f"(c[3])
        : "r"(a[0]), "r"(a[1]), "r"(a[2]), "r"(a[3]), "r"(b[0]), "r"(b[1]));
}

// ============== mma.sync fp16 2-limb 3-pass GEMM: C = A*B^T ==============
// A limbs: [M, Kp] row-major fp16.  B limbs: [N, Kp] K-major fp16.
// CTA tile 128 x NT, 8 warps (2m x 4n), warp tile 64 x (NT/4).
// EPI: 0=fp32 plain, 1=resid+dyntanh->limbs, 2=gelu(bias)+dyntanh->limbs,
//      3=tanh(gelu(bias))->fp32
template <int NT, int EPI>
__global__ __launch_bounds__(256) void mmagemm(
        const __half* __restrict__ A0, const __half* __restrict__ A1,
        const __half* __restrict__ B0, const __half* __restrict__ B1,
        int Kp,
        float* __restrict__ outF, int ldoF,
        __half* __restrict__ O0, __half* __restrict__ O1, int ldoL,
        const float* __restrict__ bias, const float* __restrict__ resid, int ldr,
        const float* __restrict__ alpha_p,
        const float* __restrict__ gv, const float* __restrict__ bv) {
    __shared__ __half As[128][72];
    __shared__ __half Bs[NT][72];
    constexpr int NF = NT / 32;   // n-frags per warp (8 cols each)

    int tid = threadIdx.x, lane = tid & 31, wid = tid >> 5;
    int wm = wid & 1, wn = wid >> 1;
    int bm = blockIdx.y * 128, bn = blockIdx.x * NT;
    int nch = Kp >> 6;

    float acc[4][NF][4];
#pragma unroll
    for (int i = 0; i < 4; i++)
#pragma unroll
        for (int j = 0; j < NF; j++)
#pragma unroll
            for (int c = 0; c < 4; c++) acc[i][j][c] = 0.f;

    // 3 passes: h0*g0, h0*g1, h1*g0 (residual ~2^-22)
    const int laT[3] = {0, 0, 1};
    const int lbT[3] = {0, 1, 0};

#pragma unroll 1
    for (int t = 0; t < 3; t++) {
        const __half* Ab = (laT[t] == 0) ? A0 : A1;
        const __half* Bb = (lbT[t] == 0) ? B0 : B1;
#pragma unroll 1
        for (int c = 0; c < nch; c++) {
            __syncthreads();   // previous chunk's compute done
            const __half* Asrc = Ab + (size_t)bm * Kp + c * 64;
#pragma unroll
            for (int q = 0; q < 4; q++) {
                int idx = tid + q * 256;
                int row = idx >> 3, cg = idx & 7;
                uint4 v = *(const uint4*)(Asrc + (size_t)row * Kp + cg * 8);
                *(uint4*)&As[row][cg * 8] = v;
            }
            const __half* Bsrc = Bb + (size_t)bn * Kp + c * 64;
#pragma unroll
            for (int q = 0; q < NF; q++) {
                int idx = tid + q * 256;
                int row = idx >> 3, cg = idx & 7;
                uint4 v = *(const uint4*)(Bsrc + (size_t)row * Kp + cg * 8);
                *(uint4*)&Bs[row][cg * 8] = v;
            }
            __syncthreads();

#pragma unroll
            for (int kk = 0; kk < 4; kk++) {
                int k = kk * 16;
                uint32_t a[4][4];
#pragma unroll
                for (int i = 0; i < 4; i++) {
                    int row = wm * 64 + i * 16 + (lane & 15);
                    int col = k + (lane >> 4) * 8;
                    ldsm4(a[i], smem_u32(&As[row][col]));
                }
                uint32_t b[NF][2];
#pragma unroll
                for (int jj = 0; jj < NF / 2; jj++) {
                    int n0 = wn * (NT / 4) + jj * 16;
                    int g = lane >> 3;
                    int nr = n0 + ((g >> 1) << 3) + (lane & 7);
                    int kc = k + (g & 1) * 8;
                    uint32_t tmp[4];
                    ldsm4(tmp, smem_u32(&Bs[nr][kc]));
                    b[2 * jj][0] = tmp[0]; b[2 * jj][1] = tmp[1];
                    b[2 * jj + 1][0] = tmp[2]; b[2 * jj + 1][1] = tmp[3];
                }
#pragma unroll
                for (int i = 0; i < 4; i++)
#pragma unroll
                    for (int j = 0; j < NF; j++) mma16816(acc[i][j], a[i], b[j]);
            }
        }
    }

    // ---------------- epilogue ----------------
    float alpha = (EPI == 1 || EPI == 2) ? *alpha_p : 0.f;
    int gid = lane >> 2, tig = lane & 3;
#pragma unroll
    for (int i = 0; i < 4; i++) {
#pragma unroll
        for (int j = 0; j < NF; j++) {
#pragma unroll
            for (int cc = 0; cc < 4; cc++) {
                int m = bm + wm * 64 + i * 16 + gid + (cc >> 1) * 8;
                int ncol = bn + wn * (NT / 4) + j * 8 + tig * 2 + (cc & 1);
                float v = acc[i][j][cc];
                if (EPI == 0) {
                    outF[(size_t)m * ldoF + ncol] = v;
                } else if (EPI == 1) {
                    v += resid[(size_t)m * ldr + ncol];
                    v = tanhf(alpha * v) * gv[ncol] + bv[ncol];
                    store2(O0, O1, (size_t)m * ldoL + ncol, v);
                } else if (EPI == 2) {
                    v = gelu_tanh(v + bias[ncol]);
                    v = tanhf(alpha * v) * gv[ncol] + bv[ncol];
                    store2(O0, O1, (size_t)m * ldoL + ncol, v);
                } else {
                    v = tanhf(gelu_tanh(v + bias[ncol]));
                    outF[(size_t)m * ldoF + ncol] = v;
                }
            }
        }
    }
}

// ---------------- conversions ----------------
__global__ void convA_kernel(const float* __restrict__ src, __half* d0, __half* d1, int n) {
    int t = blockIdx.x * blockDim.x + threadIdx.x;
    if (t >= n) return;
    store2(d0, d1, t, src[t]);
}

__global__ void convB_kernel(const float* __restrict__ src, __half* d0, __half* d1,
                             int K, int N, int Kp) {
    int t = blockIdx.x * blockDim.x + threadIdx.x;
    if (t >= N * K) return;
    int n = t / K, k = t - n * K;
    store2(d0, d1, (size_t)n * Kp + k, src[(size_t)k * N + n]);
}

__global__ void convBqkv_kernel(const float* __restrict__ Wq, const float* __restrict__ Wk,
                                const float* __restrict__ Wv, __half* d0, __half* d1) {
    int t = blockIdx.x * blockDim.x + threadIdx.x;
    if (t >= QKVW * CC) return;
    int n = t >> 8, k = t & 255;
    const float* s = (n < 512) ? Wq : ((n < 1024) ? Wk : Wv);
    int col = n & 511;
    store2(d0, d1, (size_t)n * CC + k, s[(size_t)k * 512 + col]);
}

// ---------------- gate projection ----------------
__global__ void gate_kernel(const float* __restrict__ x, const float* __restrict__ wg) {
    int t = blockIdx.x * blockDim.x + threadIdx.x;
    if (t >= NN * HH) return;
    int n = t >> 3, h = t & 7;
    const float* xr = x + (size_t)n * CC;
    float acc = 0.f;
#pragma unroll 4
    for (int c = 0; c < CC; c++) acc = fmaf(xr[c], wg[c * HH + h], acc);
    g_G[t] = acc;
}

// ---------------- attention: block per node, warp per head; writes Att limbs ------
__global__ void attn_kernel(const float* __restrict__ coors, const int* __restrict__ nbr,
                            const float* __restrict__ Wr1, const float* __restrict__ br1,
                            const float* __restrict__ Wr2, const float* __restrict__ br2) {
    int n = blockIdx.x;
    int tid = threadIdx.x;
    __shared__ int s_nbr[8];
    __shared__ float s_dist[8];
    __shared__ float s_unit[8][3];
    __shared__ float s_rad[8][8];
    __shared__ float s_gate[8][8];

    if (tid < 8) s_nbr[tid] = nbr[(size_t)n * 8 + tid];
    __syncthreads();
    if (tid < 8) {
        int j = tid;
        float cx = coors[(size_t)n * 3], cy = coors[(size_t)n * 3 + 1], cz = coors[(size_t)n * 3 + 2];
        int mm = s_nbr[j];
        float rx = coors[(size_t)mm * 3] - cx;
        float ry = coors[(size_t)mm * 3 + 1] - cy;
        float rz = coors[(size_t)mm * 3 + 2] - cz;
        float d = sqrtf(rx * rx + ry * ry + rz * rz + 1e-8f);
        s_dist[j] = d;
        s_unit[j][0] = rx / d;
        s_unit[j][1] = ry / d;
        s_unit[j][2] = rz / d;
    }
    __syncthreads();
    if (tid < 64) {
        int j = tid >> 3, h = tid & 7;
        float d = s_dist[j];
        float acc = br2[h];
#pragma unroll
        for (int i = 0; i < 16; i++)
            acc = fmaf(gelu_tanh(d * Wr1[i] + br1[i]), Wr2[i * 8 + h], acc);
        s_rad[j][h] = acc;
        s_gate[j][h] = g_G[(size_t)s_nbr[j] * HH + h];
    }
    __syncthreads();

    int w = tid >> 5, lane = tid & 31;
    int h = w;
    const float* qr = g_QKV + (size_t)n * QKVW + h * 64;
    float q0 = qr[lane * 2], q1 = qr[lane * 2 + 1];
    float logit[8];
#pragma unroll
    for (int j = 0; j < 8; j++) {
        const float* kr = g_QKV + (size_t)s_nbr[j] * QKVW + 512 + h * 64;
        float p = q0 * kr[lane * 2] + q1 * kr[lane * 2 + 1];
#pragma unroll
        for (int o = 16; o; o >>= 1) p += __shfl_xor_sync(0xffffffffu, p, o);
        p = p * 0.125f + s_rad[j][h];
        logit[j] = (s_dist[j] <= 10.0f) ? p : -1e9f;
    }
    float mx = logit[0];
#pragma unroll
    for (int j = 1; j < 8; j++) mx = fmaxf(mx, logit[j]);
    float e[8];
    float se = 0.f;
#pragma unroll
    for (int j = 0; j < 8; j++) { e[j] = expf(logit[j] - mx); se += e[j]; }
    float inv = 1.f / se;
    float a0 = 0.f, a1 = 0.f;
#pragma unroll
    for (int j = 0; j < 8; j++) {
        float at = e[j] * inv;
        const float* vr = g_QKV + (size_t)s_nbr[j] * QKVW + 1024 + h * 64;
        a0 = fmaf(at, vr[lane * 2], a0);
        a1 = fmaf(at, vr[lane * 2 + 1], a1);
    }
    size_t base = (size_t)n * ATTKP + h * 64 + lane * 2;
    store2(g_Al0, g_Al1, base, a0);
    store2(g_Al0, g_Al1, base + 1, a1);
    if (lane == 0) {
        float vx = 0.f, vy = 0.f, vz = 0.f;
#pragma unroll
        for (int j = 0; j < 8; j++) {
            float wg = e[j] * inv * s_gate[j][h];
            vx = fmaf(wg, s_unit[j][0], vx);
            vy = fmaf(wg, s_unit[j][1], vy);
            vz = fmaf(wg, s_unit[j][2], vz);
        }
        float vn = sqrtf(vx * vx + vy * vy + vz * vz + 1e-8f);
        store2(g_Al0, g_Al1, (size_t)n * ATTKP + 512 + h, vn);
    }
}

// ---------------- H2 extra columns (aa feats through dyntanh2) -> limbs ----------
__global__ void h2extra_kernel(const float* __restrict__ x, const float* __restrict__ alpha2,
                               const float* __restrict__ g2, const float* __restrict__ b2) {
    int t = blockIdx.x * blockDim.x + threadIdx.x;
    if (t >= NN * 20) return;
    int n = t / 20, j = t % 20;
    float a = *alpha2;
    float v = tanhf(a * x[(size_t)n * CC + j]) * g2[512 + j] + b2[512 + j];
    store2(g_Hl0, g_Hl1, (size_t)n * H2KP + 512 + j, v);
}

// ---------------- VQ: argmin + quantize + commitment loss ----------------
__global__ void zero_loss_kernel() { g_loss = 0.0; }

__global__ void vq_kernel(const float* __restrict__ cb, float* __restrict__ out) {
    int n = blockIdx.x;
    int t = threadIdx.x;  // 64
    __shared__ float s_z[64];
    __shared__ float s_sc[64];
    __shared__ int s_best;
    s_z[t] = g_Z[(size_t)n * 64 + t];
    __syncthreads();
    float dot = 0.f, cn = 0.f;
    const float* ce = cb + (size_t)t * 64;
#pragma unroll 8
    for (int d = 0; d < 64; d++) {
        float c = ce[d];
        dot = fmaf(s_z[d], c, dot);
        cn = fmaf(c, c, cn);
    }
    s_sc[t] = cn - 2.f * dot;
    __syncthreads();
    if (t == 0) {
        float best = s_sc[0];
        int bi = 0;
        for (int e2 = 1; e2 < 64; e2++)
            if (s_sc[e2] < best) { best = s_sc[e2]; bi = e2; }
        s_best = bi;
    }
    __syncthreads();
    float zq = cb[(size_t)s_best * 64 + t];
    out[(size_t)n * 64 + t] = zq;
    float df = s_z[t] - zq;
    df = df * df;
#pragma unroll
    for (int o = 16; o; o >>= 1) df += __shfl_xor_sync(0xffffffffu, df, o);
    __shared__ float s_part[2];
    if ((t & 31) == 0) s_part[t >> 5] = df;
    __syncthreads();
    if (t == 0) atomicAdd(&g_loss, (double)(s_part[0] + s_part[1]));
}

__global__ void fin_loss_kernel(float* __restrict__ out) {
    out[(size_t)NN * OUTD] = (float)(0.25 * g_loss / (double)((size_t)NN * OUTD));
}

// ---------------- launch ----------------
extern "C" void kernel_launch(void* const* d_in, const int* in_sizes, int n_in,
                              void* d_out, int out_size) {
    const float *x, *coors, *Wq, *Wk, *Wv, *wg, *Wr1, *br1, *Wr2, *br2, *Wo;
    const float *a1, *g1, *b1, *Wlin, *blin, *a2, *g2, *b2, *Wout, *bout, *cb;
    const int* nbr;

    if (n_in > 5 && in_sizes[5] == 2048) {
        x = (const float*)d_in[0];   coors = (const float*)d_in[1];
        Wq = (const float*)d_in[2];  Wk = (const float*)d_in[3];  Wv = (const float*)d_in[4];
        wg = (const float*)d_in[5];  Wr1 = (const float*)d_in[6]; br1 = (const float*)d_in[7];
        Wr2 = (const float*)d_in[8]; br2 = (const float*)d_in[9]; Wo = (const float*)d_in[10];
        a1 = (const float*)d_in[11]; g1 = (const float*)d_in[12]; b1 = (const float*)d_in[13];
        Wlin = (const float*)d_in[14]; blin = (const float*)d_in[15];
        a2 = (const float*)d_in[16]; g2 = (const float*)d_in[17]; b2 = (const float*)d_in[18];
        Wout = (const float*)d_in[19]; bout = (const float*)d_in[20];
        cb = (const float*)d_in[21]; nbr = (const int*)d_in[22];
    } else {
        x = (const float*)d_in[0];   coors = (const float*)d_in[1];
        nbr = (const int*)d_in[2];
        Wq = (const float*)d_in[3];  Wk = (const float*)d_in[4];  Wv = (const float*)d_in[5];
        wg = (const float*)d_in[6];  Wr1 = (const float*)d_in[7]; br1 = (const float*)d_in[8];
        Wr2 = (const float*)d_in[9]; br2 = (const float*)d_in[10]; Wo = (const float*)d_in[11];
        a1 = (const float*)d_in[12]; g1 = (const float*)d_in[13]; b1 = (const float*)d_in[14];
        Wlin = (const float*)d_in[15]; blin = (const float*)d_in[16];
        a2 = (const float*)d_in[17]; g2 = (const float*)d_in[18]; b2 = (const float*)d_in[19];
        Wout = (const float*)d_in[20]; bout = (const float*)d_in[21];
        cb = (const float*)d_in[22];
    }

    float *pQKV, *pZ;
    cudaGetSymbolAddress((void**)&pQKV, g_QKV);
    cudaGetSymbolAddress((void**)&pZ, g_Z);
    __half *xl0, *xl1, *Al0, *Al1, *Tl0, *Tl1, *Hl0, *Hl1;
    cudaGetSymbolAddress((void**)&xl0, g_xl0); cudaGetSymbolAddress((void**)&xl1, g_xl1);
    cudaGetSymbolAddress((void**)&Al0, g_Al0); cudaGetSymbolAddress((void**)&Al1, g_Al1);
    cudaGetSymbolAddress((void**)&Tl0, g_Tl0); cudaGetSymbolAddress((void**)&Tl1, g_Tl1);
    cudaGetSymbolAddress((void**)&Hl0, g_Hl0); cudaGetSymbolAddress((void**)&Hl1, g_Hl1);
    __half *Bq0, *Bq1, *Bo0, *Bo1, *Bl0, *Bl1, *Bu0, *Bu1;
    cudaGetSymbolAddress((void**)&Bq0, g_Bq0); cudaGetSymbolAddress((void**)&Bq1, g_Bq1);
    cudaGetSymbolAddress((void**)&Bo0, g_Bo0); cudaGetSymbolAddress((void**)&Bo1, g_Bo1);
    cudaGetSymbolAddress((void**)&Bl0, g_Bl0); cudaGetSymbolAddress((void**)&Bl1, g_Bl1);
    cudaGetSymbolAddress((void**)&Bu0, g_Bu0); cudaGetSymbolAddress((void**)&Bu1, g_Bu1);

    float* out = (float*)d_out;

    zero_loss_kernel<<<1, 1>>>();

    // conversions: x and weights -> fp16 limbs
    convA_kernel<<<(NN * CC + 255) / 256, 256>>>(x, xl0, xl1, NN * CC);
    convBqkv_kernel<<<(QKVW * CC + 255) / 256, 256>>>(Wq, Wk, Wv, Bq0, Bq1);
    convB_kernel<<<(CC * 520 + 255) / 256, 256>>>(Wo, Bo0, Bo1, 520, CC, ATTKP);
    convB_kernel<<<(HIDD * CC + 255) / 256, 256>>>(Wlin, Bl0, Bl1, CC, HIDD, CC);
    convB_kernel<<<(OUTD * 532 + 255) / 256, 256>>>(Wout, Bu0, Bu1, 532, OUTD, H2KP);

    // QKV = x @ [Wq|Wk|Wv]  -> fp32
    mmagemm<128, 0><<<dim3(QKVW / 128, NN / 128), 256>>>(
        xl0, xl1, Bq0, Bq1, CC,
        pQKV, QKVW, nullptr, nullptr, 0,
        nullptr, nullptr, 0, nullptr, nullptr, nullptr);

    gate_kernel<<<(NN * HH + 255) / 256, 256>>>(x, wg);
    attn_kernel<<<NN, 256>>>(coors, nbr, Wr1, br1, Wr2, br2);

    // T = dyntanh(x + Att@Wo) -> limbs
    mmagemm<128, 1><<<dim3(CC / 128, NN / 128), 256>>>(
        Al0, Al1, Bo0, Bo1, ATTKP,
        nullptr, 0, Tl0, Tl1, CC,
        nullptr, x, CC, a1, g1, b1);

    // H2[:, :512] = dyntanh2(gelu(T@Wlin + blin)) -> limbs
    mmagemm<128, 2><<<dim3(HIDD / 128, NN / 128), 256>>>(
        Tl0, Tl1, Bl0, Bl1, CC,
        nullptr, 0, Hl0, Hl1, H2KP,
        blin, nullptr, 0, a2, g2, b2);
    h2extra_kernel<<<(NN * 20 + 255) / 256, 256>>>(x, a2, g2, b2);

    // Z = tanh(gelu(H2@Wout + bout)) -> fp32
    mmagemm<64, 3><<<dim3(1, NN / 128), 256>>>(
        Hl0, Hl1, Bu0, Bu1, H2KP,
        pZ, OUTD, nullptr, nullptr, 0,
        bout, nullptr, 0, nullptr, nullptr, nullptr);

    vq_kernel<<<NN, 64>>>(cb, out);
    if (out_size > NN * OUTD) fin_loss_kernel<<<1, 1>>>(out);
}